// round 10
// baseline (speedup 1.0000x reference)
#include <cuda_runtime.h>

#define HLOG2E 0.7213475204444817f   // log2(e)/2
#define EPS    1e-8f

__device__ float        g_partials[8192];
__device__ unsigned int g_done;   // zero-init; last CTA resets -> graph-replay safe

__device__ __forceinline__ float ex2a(float x) {
    float r; asm("ex2.approx.ftz.f32 %0, %1;" : "=f"(r) : "f"(x)); return r;
}
__device__ __forceinline__ float lg2a(float x) {
    float r; asm("lg2.approx.ftz.f32 %0, %1;" : "=f"(r) : "f"(x)); return r;
}

// Pair identity: log2(sig(d)) + log2(sig(-d)) = -2*log2(2^{d/2} + 2^{-d/2}).
// With Q = 2^{s*log2e/2}, R = 1/Q:  2^{d/2} = Qi*Rj,  2^{-d/2} = Ri*Qj.
// Gains prescaled by 2 so contribution = -|g2i - g2j| * lg2(Qi*Rj + Ri*Qj).
__device__ __forceinline__ float pair_term(float Q, float R, float g2, float4 p) {
    const float v  = fmaf(Q, p.y, R * p.x);     // FMUL + FFMA
    const float l  = lg2a(v);                   // MUFU.LG2 (v >= 2 > 0)
    const float gd = g2 - p.z;                  // FADD
    return fabsf(gd) * l;
}

// Block-per-row, 128 threads. Row staged in smem as (Q, R, 2*gain, 0) with the
// first 64 entries mirrored past L so partner index i+k never wraps. Primary
// slots i>=L are never read (mirror covers [L, L+63]); each thread writes only
// its own slots -> one barrier before the loop.
__global__ void __launch_bounds__(128) ndcg_kernel(
    const float* __restrict__ scores,
    const int*   __restrict__ relev,
    const int*   __restrict__ qlen,
    float*       __restrict__ out,
    int D, int B)
{
    const int b = blockIdx.x;
    const int i = threadIdx.x;          // 0..127 = D

    __shared__ float4 s_sg[192];
    __shared__ int    s_cnt[8];
    __shared__ float  s_rn[4], s_ri[4];
    __shared__ int    s_last;

    const int  L     = qlen[b];
    const bool valid = (i < L);

    const float sc = scores[b * D + i];
    const int   rv = relev[b * D + i];

    const float Q  = ex2a(sc * HLOG2E);           // 2^{s*log2e/2}
    const float R  = ex2a(sc * (-HLOG2E));        // 2^{-s*log2e/2}
    const float g2 = valid ? (float)(2 * ((1 << rv) - 1)) : 0.0f;

    const float4 mine = make_float4(Q, R, g2, 0.0f);
    if (i < 8) s_cnt[i] = 0;
    if (valid)  s_sg[i] = mine;          // primary (only valid slots read)
    if (i < 64) s_sg[L + i] = mine;      // mirror covers [L, L+63]
    __syncthreads();
    if (valid) atomicAdd(&s_cnt[rv], 1);
    __syncthreads();

    // ---- pairwise sum, cyclic-distance enumeration, 4 independent chains ----
    float num = 0.0f;
    if (valid && L > 1) {
        const int     halfm = (L - 1) >> 1;
        const float4* base  = &s_sg[i];
        float n0 = 0.0f, n1 = 0.0f, n2 = 0.0f, n3 = 0.0f;

        int k = 1;
        for (; k + 3 <= halfm; k += 4) {
            n0 -= pair_term(Q, R, g2, base[k]);
            n1 -= pair_term(Q, R, g2, base[k + 1]);
            n2 -= pair_term(Q, R, g2, base[k + 2]);
            n3 -= pair_term(Q, R, g2, base[k + 3]);
        }
        for (; k <= halfm; ++k)
            n0 -= pair_term(Q, R, g2, base[k]);

        // tie distance k=L/2 (L even): counted once, by i < L/2 (no wrap)
        if (((L & 1) == 0) && (i < (L >> 1)))
            n1 -= pair_term(Q, R, g2, s_sg[i + (L >> 1)]);

        num = (n0 + n1) + (n2 + n3);
    }

    // ---- ideal DCG via counting sort (gains in {0,1,3,7,15}) ----
    float idl = 0.0f;
    if (valid) {
        const int c4 = s_cnt[4];
        const int c3 = c4 + s_cnt[3];
        const int c2 = c3 + s_cnt[2];
        const int c1 = c2 + s_cnt[1];
        float gr;
        if      (i < c4) gr = 15.0f;
        else if (i < c3) gr = 7.0f;
        else if (i < c2) gr = 3.0f;
        else if (i < c1) gr = 1.0f;
        else             gr = 0.0f;
        idl = __fdividef(gr, lg2a((float)(i + 2)));
    }

    // ---- block reduction of (num, idl) ----
    #pragma unroll
    for (int off = 16; off > 0; off >>= 1) {
        num += __shfl_down_sync(0xFFFFFFFFu, num, off);
        idl += __shfl_down_sync(0xFFFFFFFFu, idl, off);
    }
    const int wid  = i >> 5;
    const int lane = i & 31;
    if (lane == 0) { s_rn[wid] = num; s_ri[wid] = idl; }
    __syncthreads();
    if (i == 0) {
        const float n  = (s_rn[0] + s_rn[1]) + (s_rn[2] + s_rn[3]);
        const float id = (s_ri[0] + s_ri[1]) + (s_ri[2] + s_ri[3]);
        g_partials[b] = -n / (id + EPS);
        __threadfence();
        const unsigned int t = atomicAdd(&g_done, 1u);
        s_last = (t == (unsigned int)(gridDim.x - 1));
    }
    __syncthreads();

    // ---- last CTA: deterministic final reduction ----
    if (s_last) {
        __threadfence();
        float s = 0.0f;
        for (int r = i; r < B; r += 128) s += g_partials[r];
        #pragma unroll
        for (int off = 16; off > 0; off >>= 1)
            s += __shfl_down_sync(0xFFFFFFFFu, s, off);
        if (lane == 0) s_rn[wid] = s;
        __syncthreads();
        if (i == 0) {
            out[0] = ((s_rn[0] + s_rn[1]) + (s_rn[2] + s_rn[3])) / (float)B;
            g_done = 0;   // reset for next graph replay
        }
    }
}

extern "C" void kernel_launch(void* const* d_in, const int* in_sizes, int n_in,
                              void* d_out, int out_size)
{
    const float* scores = (const float*)d_in[0];
    const int*   relev  = (const int*)  d_in[1];
    const int*   qlen   = (const int*)  d_in[2];
    float*       out    = (float*)      d_out;

    const int B = in_sizes[2];
    const int D = in_sizes[0] / B;   // 128

    ndcg_kernel<<<B, 128>>>(scores, relev, qlen, out, D, B);
}

// round 11
// speedup vs baseline: 1.0850x; 1.0850x over previous
#include <cuda_runtime.h>

#define LOG2E 1.4426950408889634f
#define EPS   1e-8f

__device__ float        g_partials[8192];
__device__ unsigned int g_done;   // zero-init; last CTA resets -> graph-replay safe

__device__ __forceinline__ float ex2a(float x) {
    float r; asm("ex2.approx.ftz.f32 %0, %1;" : "=f"(r) : "f"(x)); return r;
}
__device__ __forceinline__ float lg2a(float x) {
    float r; asm("lg2.approx.ftz.f32 %0, %1;" : "=f"(r) : "f"(x)); return r;
}

// One unordered pair, both orders folded. si is score*log2e.
// nm = -|si-sj|;  term = |gi-gj| * (-nm + 2*log2(1 + 2^{nm}))
__device__ __forceinline__ float pair_term(float si, float gi, float2 p) {
    const float d  = si - p.x;
    const float nm = 0.0f - fabsf(d);
    const float u  = ex2a(nm);                 // MUFU.EX2
    const float l  = lg2a(1.0f + u);           // MUFU.LG2
    const float q  = fmaf(2.0f, l, -nm);
    return fabsf(gi - p.y) * q;
}

// Block-per-row, 256 threads = 2 k-parity groups of 128. Group h covers cyclic
// distances k = 1+h, 3+h, ... — halves the serial path per row. Row staged in
// smem as (score*log2e, gain) by group 0; first 64 entries mirrored past L so
// partner index i+k never wraps.
__global__ void __launch_bounds__(256) ndcg_kernel(
    const float* __restrict__ scores,
    const int*   __restrict__ relev,
    const int*   __restrict__ qlen,
    float*       __restrict__ out,
    int D, int B)
{
    const int tid = threadIdx.x;
    const int b   = blockIdx.x;
    const int i   = tid & 127;          // doc index
    const int h   = tid >> 7;           // k-parity group

    __shared__ float2 s_sg[192];
    __shared__ int    s_cnt[8];
    __shared__ float  s_rn[8], s_ri[8];
    __shared__ int    s_last;

    const int  L     = qlen[b];
    const bool valid = (i < L);

    float sv = 0.0f, gv = 0.0f;
    if (h == 0) {
        sv = scores[b * D + i] * LOG2E;
        const int rv = relev[b * D + i];
        gv = valid ? (float)((1 << rv) - 1) : 0.0f;   // 2^rel - 1
        const float2 mine = make_float2(sv, gv);
        if (i < 8)  s_cnt[i] = 0;
        if (valid)  s_sg[i] = mine;        // primary (only valid slots read)
        if (i < 64) s_sg[L + i] = mine;    // mirror covers [L, L+63]
    }
    __syncthreads();
    if (h == 0 && valid) atomicAdd(&s_cnt[relev[b * D + i] & 7], 1);
    if (h == 1 && valid) { const float2 m = s_sg[i]; sv = m.x; gv = m.y; }
    __syncthreads();

    // ---- this group's share of the pairwise sum (4 independent chains) ----
    float num = 0.0f;
    if (valid && L > 1) {
        const int     halfm = (L - 1) >> 1;
        const float2* base  = &s_sg[i];
        float n0 = 0.0f, n1 = 0.0f, n2 = 0.0f, n3 = 0.0f;

        int k = 1 + h;
        for (; k + 6 <= halfm; k += 8) {       // 4 pairs/trip, stride 2
            n0 -= pair_term(sv, gv, base[k]);
            n1 -= pair_term(sv, gv, base[k + 2]);
            n2 -= pair_term(sv, gv, base[k + 4]);
            n3 -= pair_term(sv, gv, base[k + 6]);
        }
        for (; k <= halfm; k += 2)
            n0 -= pair_term(sv, gv, base[k]);

        // tie distance k=L/2 (L even): counted once, by group 1, i < L/2
        if ((h == 1) && ((L & 1) == 0) && (i < (L >> 1)))
            n1 -= pair_term(sv, gv, s_sg[i + (L >> 1)]);

        num = (n0 + n1) + (n2 + n3);
    }

    // ---- ideal DCG via counting sort (group 0 only; gains in {0,1,3,7,15}) ----
    float idl = 0.0f;
    if (h == 0 && valid) {
        const int c4 = s_cnt[4];
        const int c3 = c4 + s_cnt[3];
        const int c2 = c3 + s_cnt[2];
        const int c1 = c2 + s_cnt[1];
        float gr;
        if      (i < c4) gr = 15.0f;
        else if (i < c3) gr = 7.0f;
        else if (i < c2) gr = 3.0f;
        else if (i < c1) gr = 1.0f;
        else             gr = 0.0f;
        idl = __fdividef(gr, lg2a((float)(i + 2)));
    }

    // ---- block reduction of (num, idl) across 8 warps ----
    #pragma unroll
    for (int off = 16; off > 0; off >>= 1) {
        num += __shfl_down_sync(0xFFFFFFFFu, num, off);
        idl += __shfl_down_sync(0xFFFFFFFFu, idl, off);
    }
    const int wid  = tid >> 5;
    const int lane = tid & 31;
    if (lane == 0) { s_rn[wid] = num; s_ri[wid] = idl; }
    __syncthreads();
    if (tid == 0) {
        float n = 0.0f, id = 0.0f;
        #pragma unroll
        for (int w = 0; w < 8; ++w) { n += s_rn[w]; id += s_ri[w]; }
        g_partials[b] = -n / (id + EPS);
        __threadfence();
        const unsigned int t = atomicAdd(&g_done, 1u);
        s_last = (t == (unsigned int)(gridDim.x - 1));
    }
    __syncthreads();

    // ---- last CTA: deterministic final reduction ----
    if (s_last) {
        __threadfence();
        float s = 0.0f;
        for (int r = tid; r < B; r += 256) s += g_partials[r];
        #pragma unroll
        for (int off = 16; off > 0; off >>= 1)
            s += __shfl_down_sync(0xFFFFFFFFu, s, off);
        if (lane == 0) s_rn[wid] = s;
        __syncthreads();
        if (tid == 0) {
            float t = 0.0f;
            #pragma unroll
            for (int w = 0; w < 8; ++w) t += s_rn[w];
            out[0] = t / (float)B;
            g_done = 0;   // reset for next graph replay
        }
    }
}

extern "C" void kernel_launch(void* const* d_in, const int* in_sizes, int n_in,
                              void* d_out, int out_size)
{
    const float* scores = (const float*)d_in[0];
    const int*   relev  = (const int*)  d_in[1];
    const int*   qlen   = (const int*)  d_in[2];
    float*       out    = (float*)      d_out;

    const int B = in_sizes[2];
    const int D = in_sizes[0] / B;   // 128

    ndcg_kernel<<<B, 256>>>(scores, relev, qlen, out, D, B);
}

// round 12
// speedup vs baseline: 1.2955x; 1.1940x over previous
#include <cuda_runtime.h>

#define HLOG2E 0.7213475204444817f   // log2(e)/2
#define EPS    1e-8f

__device__ float        g_partials[8192];
__device__ unsigned int g_done;   // zero-init; last CTA resets -> graph-replay safe

__device__ __forceinline__ float ex2a(float x) {
    float r; asm("ex2.approx.ftz.f32 %0, %1;" : "=f"(r) : "f"(x)); return r;
}
__device__ __forceinline__ float lg2a(float x) {
    float r; asm("lg2.approx.ftz.f32 %0, %1;" : "=f"(r) : "f"(x)); return r;
}

// Pair identity: log2(sig(d)) + log2(sig(-d)) = -2*lg2(2^{d/2} + 2^{-d/2}).
// Q = 2^{s*log2e/2} = e^{s/2}, R = 1/Q. Gains prescaled by 2, so the folded
// contribution of unordered pair {i,j} is  -|g2i - g2j| * lg2(Qi*Rj + Ri*Qj).
// ONE MUFU per pair (vs two in the direct form).

// Block-per-row, 128 threads. Row staged as s_QR (Q,R) + s_g2 (2*gain), first
// 64 entries mirrored past L so partner index i+k never wraps. Each thread
// writes only its own slots -> one barrier before the loop.
__global__ void __launch_bounds__(128, 12) ndcg_kernel(
    const float* __restrict__ scores,
    const int*   __restrict__ relev,
    const int*   __restrict__ qlen,
    float*       __restrict__ out,
    int D, int B)
{
    const int b = blockIdx.x;
    const int i = threadIdx.x;          // 0..127 = D

    __shared__ float2 s_QR[192];
    __shared__ float  s_g2[192];
    __shared__ int    s_cnt[8];
    __shared__ float  s_rn[4], s_ri[4];
    __shared__ int    s_last;

    const int  L     = qlen[b];
    const bool valid = (i < L);

    const float sc = scores[b * D + i];
    const int   rv = relev[b * D + i];

    const float Q  = ex2a(sc * HLOG2E);       // e^{s/2}
    const float R  = ex2a(sc * (-HLOG2E));    // e^{-s/2}
    const float g2 = valid ? (float)(2 * ((1 << rv) - 1)) : 0.0f;

    const float2 qr = make_float2(Q, R);
    if (i < 8) s_cnt[i] = 0;
    if (valid)  { s_QR[i] = qr;     s_g2[i] = g2; }     // primary
    if (i < 64) { s_QR[L + i] = qr; s_g2[L + i] = g2; } // mirror [L, L+63]
    __syncthreads();
    if (valid) atomicAdd(&s_cnt[rv], 1);
    __syncthreads();

    // ---- pairwise sum, cyclic-distance enumeration, 2 chains ----
    float num = 0.0f;
    if (valid && L > 1) {
        const int     halfm = (L - 1) >> 1;
        const float2* bq = &s_QR[i];
        const float*  bg = &s_g2[i];
        float n0 = 0.0f, n1 = 0.0f;

        int k = 1;
        for (; k + 1 <= halfm; k += 2) {
            const float2 p0 = bq[k];
            const float2 p1 = bq[k + 1];
            const float  v0 = fmaf(Q, p0.y, R * p0.x);   // Qi*Rj + Ri*Qj
            const float  v1 = fmaf(Q, p1.y, R * p1.x);
            const float  l0 = lg2a(v0);                  // MUFU.LG2
            const float  l1 = lg2a(v1);
            const float  d0 = g2 - bg[k];
            const float  d1 = g2 - bg[k + 1];
            n0 = fmaf(-fabsf(d0), l0, n0);
            n1 = fmaf(-fabsf(d1), l1, n1);
        }
        if (k <= halfm) {
            const float2 p0 = bq[k];
            const float  v0 = fmaf(Q, p0.y, R * p0.x);
            n0 = fmaf(-fabsf(g2 - bg[k]), lg2a(v0), n0);
        }
        // tie distance k=L/2 (L even): counted once, by i < L/2 (no wrap)
        if (((L & 1) == 0) && (i < (L >> 1))) {
            const int    m  = L >> 1;
            const float2 p0 = s_QR[i + m];
            const float  v0 = fmaf(Q, p0.y, R * p0.x);
            n1 = fmaf(-fabsf(g2 - s_g2[i + m]), lg2a(v0), n1);
        }
        num = n0 + n1;
    }

    // ---- ideal DCG via counting sort (gains in {0,1,3,7,15}) ----
    float idl = 0.0f;
    if (valid) {
        const int c4 = s_cnt[4];
        const int c3 = c4 + s_cnt[3];
        const int c2 = c3 + s_cnt[2];
        const int c1 = c2 + s_cnt[1];
        float gr;
        if      (i < c4) gr = 15.0f;
        else if (i < c3) gr = 7.0f;
        else if (i < c2) gr = 3.0f;
        else if (i < c1) gr = 1.0f;
        else             gr = 0.0f;
        idl = __fdividef(gr, lg2a((float)(i + 2)));
    }

    // ---- block reduction of (num, idl) ----
    #pragma unroll
    for (int off = 16; off > 0; off >>= 1) {
        num += __shfl_down_sync(0xFFFFFFFFu, num, off);
        idl += __shfl_down_sync(0xFFFFFFFFu, idl, off);
    }
    const int wid  = i >> 5;
    const int lane = i & 31;
    if (lane == 0) { s_rn[wid] = num; s_ri[wid] = idl; }
    __syncthreads();
    if (i == 0) {
        const float n  = (s_rn[0] + s_rn[1]) + (s_rn[2] + s_rn[3]);
        const float id = (s_ri[0] + s_ri[1]) + (s_ri[2] + s_ri[3]);
        // num here sums  -|g2i-g2j| * 2*lg2(...)  halves: the factor 2 came
        // from prescaling gains; result is the full ordered-pair numerator.
        g_partials[b] = -n / (id + EPS);
        __threadfence();
        const unsigned int t = atomicAdd(&g_done, 1u);
        s_last = (t == (unsigned int)(gridDim.x - 1));
    }
    __syncthreads();

    // ---- last CTA: deterministic final reduction ----
    if (s_last) {
        __threadfence();
        float s = 0.0f;
        for (int r = i; r < B; r += 128) s += g_partials[r];
        #pragma unroll
        for (int off = 16; off > 0; off >>= 1)
            s += __shfl_down_sync(0xFFFFFFFFu, s, off);
        if (lane == 0) s_rn[wid] = s;
        __syncthreads();
        if (i == 0) {
            out[0] = ((s_rn[0] + s_rn[1]) + (s_rn[2] + s_rn[3])) / (float)B;
            g_done = 0;   // reset for next graph replay
        }
    }
}

extern "C" void kernel_launch(void* const* d_in, const int* in_sizes, int n_in,
                              void* d_out, int out_size)
{
    const float* scores = (const float*)d_in[0];
    const int*   relev  = (const int*)  d_in[1];
    const int*   qlen   = (const int*)  d_in[2];
    float*       out    = (float*)      d_out;

    const int B = in_sizes[2];
    const int D = in_sizes[0] / B;   // 128

    ndcg_kernel<<<B, 128>>>(scores, relev, qlen, out, D, B);
}